// round 1
// baseline (speedup 1.0000x reference)
#include <cuda_runtime.h>
#include <math.h>

#define D_DEPTH 128
#define BEV 128
#define CELL (BEV*BEV)
#define RES_F 0.025f
#define X_MIN_F (-1.6f)
#define Z_MAX_F 3.3f
#define MIN_DEPTH_F (0.1f + 0.0125f)   /* Z_MIN + RES/2 */
#define LOG_U3 (-1.0986f)
#define EPSC 1e-7f

// Scratch table: log class-probs, up to 4 batches. (B,3,128,128)
__device__ float g_logcp[4 * 3 * CELL];

// ---------------------------------------------------------------------------
// Kernel 1: bev_logits (B,2,128,128) -> log class probs (B,3,128,128)
// ---------------------------------------------------------------------------
__global__ void bev_table_kernel(const float* __restrict__ bev, int B) {
    int idx = blockIdx.x * blockDim.x + threadIdx.x;
    if (idx >= B * CELL) return;
    int b = idx / CELL, zx = idx - b * CELL;
    float l0 = bev[(b * 2 + 0) * CELL + zx];
    float l1 = bev[(b * 2 + 1) * CELL + zx];
    float p0 = 1.0f / (1.0f + __expf(-l0));
    float p1 = 1.0f / (1.0f + __expf(-l1));
    p0 = fminf(fmaxf(p0, EPSC), 1.0f - EPSC);
    p1 = fminf(fmaxf(p1, EPSC), 1.0f - EPSC);
    g_logcp[(b * 3 + 0) * CELL + zx] = __logf(1.0f - p1);
    g_logcp[(b * 3 + 1) * CELL + zx] = __logf(p1 * p0);
    g_logcp[(b * 3 + 2) * CELL + zx] = __logf(p1 * (1.0f - p0));
}

// ---------------------------------------------------------------------------
// Kernel 2: main decode. Block = 32 contiguous pixels (same row) x 128 depths.
// blockDim = 256 (laid out as 32 lanes x 8 warps).
// ---------------------------------------------------------------------------
__global__ __launch_bounds__(256) void decode_kernel(
    const float* __restrict__ dl,    // (B, D, H, W)
    const float* __restrict__ invK,  // (B, 4, 4)
    float* __restrict__ out,         // (B, H, W, D, 3)
    int H, int W)
{
    __shared__ float sm[D_DEPTH][33];   // logit tile, padded pitch for conflict-free d-strided reads
    __shared__ float red[8][32];
    __shared__ float shiftv[32];        // per-pixel: first max, then -(max+lse)
    __shared__ float cam0s[32], cam1s[32], cam2s[32];

    const int tid = threadIdx.x;
    const int tx = tid & 31;            // pixel within tile
    const int ty = tid >> 5;            // warp id
    const int tilesPerRow = W >> 5;

    int bid = blockIdx.x;
    int w0 = (bid % tilesPerRow) << 5;
    int h  = (bid / tilesPerRow) % H;
    int b  =  bid / (tilesPerRow * H);

    const size_t HW = (size_t)H * W;
    const float* base = dl + ((size_t)b * D_DEPTH) * HW + (size_t)h * W + w0;

    // Phase 1: coalesced load of 128 x 32 logit tile into shared
    #pragma unroll
    for (int j = 0; j < 16; j++) {
        int d = ty + j * 8;
        sm[d][tx] = base[(size_t)d * HW + tx];
    }
    if (ty == 0) {
        const float* k = invK + (size_t)b * 16;
        float x = (float)(w0 + tx), y = (float)h;
        cam0s[tx] = k[0] * x + k[1] * y + k[2];
        cam1s[tx] = k[4] * x + k[5] * y + k[6];
        cam2s[tx] = k[8] * x + k[9] * y + k[10];
    }
    __syncthreads();

    // Phase 2a: per-pixel max over D
    float m = -INFINITY;
    #pragma unroll
    for (int j = 0; j < 16; j++) m = fmaxf(m, sm[ty + j * 8][tx]);
    red[ty][tx] = m;
    __syncthreads();
    if (ty == 0) {
        float mm = red[0][tx];
        #pragma unroll
        for (int r = 1; r < 8; r++) mm = fmaxf(mm, red[r][tx]);
        shiftv[tx] = mm;
    }
    __syncthreads();
    float mpx = shiftv[tx];

    // Phase 2b: per-pixel sum(exp(x-max))
    float s = 0.0f;
    #pragma unroll
    for (int j = 0; j < 16; j++) s += __expf(sm[ty + j * 8][tx] - mpx);
    red[ty][tx] = s;
    __syncthreads();
    if (ty == 0) {
        float ss = 0.0f;
        #pragma unroll
        for (int r = 0; r < 8; r++) ss += red[r][tx];
        shiftv[tx] = -mpx - __logf(ss);   // log_softmax shift
    }
    __syncthreads();

    // Phase 3: compute & write. Pair p = (px, d); each warp holds fixed px,
    // consecutive d -> 384 contiguous output bytes per warp instruction.
    float* outp = out + (((size_t)b * H + h) * W + w0) * (size_t)(D_DEPTH * 3);
    const float* lcp = &g_logcp[(size_t)(b * 3) * CELL];

    #pragma unroll
    for (int k2 = 0; k2 < 16; k2++) {
        int p  = tid + (k2 << 8);
        int px = p >> 7;
        int d  = p & 127;

        float dlp  = sm[d][px] + shiftv[px];
        float dval = MIN_DEPTH_F + (float)d * RES_F;
        float X =  dval * cam0s[px];
        float Y = -dval * cam1s[px];
        float Z = -dval * cam2s[px];

        int vx = (int)((X - X_MIN_F) / RES_F);   // trunc-toward-zero == astype(int32)
        int vy = (int)(Y / RES_F);
        int vz = (int)((Z + Z_MAX_F) / RES_F);

        bool valid = (vx >= 0) & (vx < BEV) & (vz >= 0) & (vz < BEV) & (vy <= 0);

        float c0, c1, c2;
        if (valid) {
            int o = vz * BEV + vx;
            c0 = lcp[o];
            c1 = lcp[o + CELL];
            c2 = lcp[o + 2 * CELL];
        } else {
            c0 = c1 = c2 = LOG_U3;
        }

        size_t oo = (size_t)px * (D_DEPTH * 3) + (size_t)d * 3;
        outp[oo + 0] = c0 + dlp;
        outp[oo + 1] = c1 + dlp;
        outp[oo + 2] = c2 + dlp;
    }
}

// ---------------------------------------------------------------------------
extern "C" void kernel_launch(void* const* d_in, const int* in_sizes, int n_in,
                              void* d_out, int out_size) {
    const float* depth = (const float*)d_in[0];   // depth_logits (B,128,H,W)
    const float* bev   = (const float*)d_in[1];   // bev_logits   (B,2,128,128)
    const float* invK  = (const float*)d_in[2];   // inv_K        (B,4,4)
    float* out = (float*)d_out;

    int B = in_sizes[2] / 16;
    long long HW = (long long)in_sizes[0] / ((long long)B * D_DEPTH);
    int W = 1;
    while ((long long)W * W < HW) W <<= 1;        // square, power-of-two dims
    int H = (int)(HW / W);

    bev_table_kernel<<<(B * CELL + 255) / 256, 256>>>(bev, B);
    decode_kernel<<<B * H * (W / 32), 256>>>(depth, invK, out, H, W);
}